// round 9
// baseline (speedup 1.0000x reference)
#include <cuda_runtime.h>
#include <cuda_fp16.h>
#include <cstdint>

#define DDIM 512
#define KDIM 512
#define BM   64
#define NTH  512
#define NCH  32      // K chunks of 16 (f16)

// static scratch (no allocations allowed)
__device__ __half g_cb[KDIM * DDIM];   // clusters fp16 [K][D]
__device__ float g_c2[KDIM];

// ---- smem layout (bytes, dynamic) ----
#define BSTAGEB 16384u                // 512 rows * 32B (k16 f16), XOR swizzle, no pad
#define OFF_A   0u                    // 64 rows * 1024B swizzled = 65536, resident
#define OFF_B   65536u                // 2 * 16384 -> 98304
#define OFF_C2  98304u                // 512*4 -> 100352
#define OFF_X2  100352u               // 64*4  -> 100608
#define OFF_RS  100608u               // 8*64*4 -> 102656
#define SMEM_TOTAL 102656u            // ~100.2 KB -> 2 CTAs/SM

// ---------------- helpers ----------------
__device__ __forceinline__ float frcp(float a) {
    float r; asm("rcp.approx.ftz.f32 %0, %1;" : "=f"(r) : "f"(a)); return r;
}
__device__ __forceinline__ uint32_t pkh(float a, float b) {
    __half2 h = __floats2half2_rn(a, b);
    return *reinterpret_cast<uint32_t*>(&h);
}
__device__ __forceinline__ void cp16(uint32_t dst, const void* src) {
    asm volatile("cp.async.cg.shared.global [%0], [%1], 16;"
                 :: "r"(dst), "l"(__cvta_generic_to_global(src)) : "memory");
}
#define CP_COMMIT() asm volatile("cp.async.commit_group;" ::: "memory")
template <int N>
__device__ __forceinline__ void cp_wait() {
    asm volatile("cp.async.wait_group %0;" :: "n"(N) : "memory");
}
__device__ __forceinline__ void ldsm4(uint32_t* r, uint32_t a) {
    asm volatile("ldmatrix.sync.aligned.m8n8.x4.shared.b16 {%0,%1,%2,%3}, [%4];"
                 : "=r"(r[0]), "=r"(r[1]), "=r"(r[2]), "=r"(r[3]) : "r"(a));
}
// fp16-accumulator HMMA (2 acc regs)
__device__ __forceinline__ void mma_f16(uint32_t* c, const uint32_t* a, uint32_t b0, uint32_t b1) {
    asm volatile("mma.sync.aligned.m16n8k16.row.col.f16.f16.f16.f16 "
                 "{%0,%1}, {%2,%3,%4,%5}, {%6,%7}, {%0,%1};"
                 : "+r"(c[0]), "+r"(c[1])
                 : "r"(a[0]), "r"(a[1]), "r"(a[2]), "r"(a[3]), "r"(b0), "r"(b1));
}

// ---------------- prep: clusters -> fp16, c2 fp32 ----------------
__global__ void prep_kernel(const float* __restrict__ clusters) {
    int k = blockIdx.x, tid = threadIdx.x;
    const float* row = clusters + (size_t)k * DDIM;
    float s = 0.f;
    for (int d = tid; d < DDIM; d += 128) {
        float v = row[d];
        s += v * v;
        g_cb[(size_t)k * DDIM + d] = __float2half(v);
    }
    #pragma unroll
    for (int o = 16; o > 0; o >>= 1) s += __shfl_xor_sync(0xffffffffu, s, o);
    __shared__ float red[4];
    if ((tid & 31) == 0) red[tid >> 5] = s;
    __syncthreads();
    if (tid == 0) g_c2[k] = red[0] + red[1] + red[2] + red[3];
}

// ---------------- main fused kernel ----------------
// CTA: 64 rows x all 512 cols. 512 threads, warp grid 2(M) x 8(N), warp tile 32x64.
// f16 accumulators (32 regs). <=64 regs/thread -> 2 CTAs/SM -> 32 warps/SM.
__global__ void __launch_bounds__(NTH, 2)
cluster_kernel(const float* __restrict__ x, float* __restrict__ out) {
    extern __shared__ char smem[];
    char*  smA = smem + OFF_A;
    float* c2s = (float*)(smem + OFF_C2);
    float* x2s = (float*)(smem + OFF_X2);
    float* rss = (float*)(smem + OFF_RS);

    const int tid = threadIdx.x, lane = tid & 31, wid = tid >> 5;
    const int wm = wid & 1, wn = wid >> 1;          // 2 x 8 warp grid
    const long row0 = (long)blockIdx.x * BM;
    const float* xblk = x + row0 * DDIM;

    const uint32_t sA = (uint32_t)__cvta_generic_to_shared(smA);
    const uint32_t sB = (uint32_t)__cvta_generic_to_shared(smem + OFF_B);

    // B loader: chunk c = k-cols [c*16, c*16+16) of all 512 rows (16 KB)
    // smem: row*32 + (seg16 ^ ((row&4)<<2))  -- conflict-free XOR swizzle
    auto loadB = [&](int c, int s) {
        #pragma unroll
        for (int i = 0; i < 2; i++) {
            int idx = tid + i * NTH;                // 0..1023
            int brow = idx >> 1, seg = (idx & 1) << 4;
            uint32_t dst = sB + s * BSTAGEB + brow * 32 + (seg ^ ((brow & 4) << 2));
            const char* src = (const char*)g_cb + (size_t)brow * (DDIM * 2) + c * 32 + seg;
            cp16(dst, src);
        }
        CP_COMMIT();
    };

    loadB(0, 0);   // prefetch chunk 0 while converting A

    for (int i = tid; i < KDIM; i += NTH) c2s[i] = g_c2[i];

    // ---- A: x fp32 -> f16 into swizzled resident smem (1024B rows), + ||x||^2 ----
    {
        const int arow = tid >> 3, a8 = tid & 7;    // 8 threads/row, 64 floats each
        const float* src = xblk + (size_t)arow * DDIM + a8 * 64;
        float x2a = 0.f;
        #pragma unroll
        for (int j = 0; j < 8; j++) {
            float4 u = *(const float4*)(src + j * 8);
            float4 v = *(const float4*)(src + j * 8 + 4);
            x2a += u.x * u.x + u.y * u.y + u.z * u.z + u.w * u.w;
            x2a += v.x * v.x + v.y * v.y + v.z * v.z + v.w * v.w;
            uint4 w = make_uint4(pkh(u.x, u.y), pkh(u.z, u.w), pkh(v.x, v.y), pkh(v.z, v.w));
            uint32_t cb = (uint32_t)(a8 * 128 + j * 16);
            *(uint4*)(smA + arow * 1024 + (cb ^ ((arow & 7u) << 4))) = w;
        }
        x2a += __shfl_xor_sync(0xffffffffu, x2a, 1);
        x2a += __shfl_xor_sync(0xffffffffu, x2a, 2);
        x2a += __shfl_xor_sync(0xffffffffu, x2a, 4);
        if ((tid & 7) == 0) x2s[arow] = x2a;
    }

    uint32_t acc[2][8][2];
    #pragma unroll
    for (int mt = 0; mt < 2; mt++)
        #pragma unroll
        for (int nt = 0; nt < 8; nt++) { acc[mt][nt][0] = 0u; acc[mt][nt][1] = 0u; }

    const uint32_t lmr = lane & 15, lmc = (lane >> 4) * 16;
    const uint32_t xr  = (lmr & 7u) << 4;                        // A swizzle term
    const uint32_t aro0 = sA + (uint32_t)(wm * 32 + lmr) * 1024u;
    const uint32_t aro1 = sA + (uint32_t)(wm * 32 + 16 + lmr) * 1024u;
    // B base: row = wn*64 + lmr; bt*16 rows -> +bt*512 bytes
    const uint32_t bro = (uint32_t)(wn * 64 + lmr) * 32u + (lmc ^ ((lmr & 4u) << 2));

    // ---- mainloop: 32 K-chunks (k16), A resident, B double-buffered ----
    #pragma unroll 1
    for (int c = 0; c < NCH; c++) {
        cp_wait<0>();
        __syncthreads();                       // chunk c visible; other stage free
        if (c + 1 < NCH) loadB(c + 1, (c + 1) & 1);

        const uint32_t acb = ((uint32_t)(c * 32) + lmc) ^ xr;
        uint32_t a0[4], a1[4];
        ldsm4(a0, aro0 + acb);
        ldsm4(a1, aro1 + acb);
        const uint32_t bbase = sB + (c & 1) * BSTAGEB + bro;
        #pragma unroll
        for (int bt = 0; bt < 4; bt++) {
            uint32_t b[4];
            ldsm4(b, bbase + bt * 512);
            mma_f16(acc[0][2 * bt + 0], a0, b[0], b[2]);
            mma_f16(acc[0][2 * bt + 1], a0, b[1], b[3]);
            mma_f16(acc[1][2 * bt + 0], a1, b[0], b[2]);
            mma_f16(acc[1][2 * bt + 1], a1, b[1], b[3]);
        }
    }

    // ---- epilogue pass 1: row sums (q in fp32, recomputed in pass 2) ----
    #pragma unroll
    for (int mt = 0; mt < 2; mt++) {
        #pragma unroll
        for (int rr = 0; rr < 2; rr++) {
            const int row = wm * 32 + mt * 16 + (lane >> 2) + rr * 8;
            const float x2v = x2s[row];
            float rsum = 0.f;
            #pragma unroll
            for (int nt = 0; nt < 8; nt++) {
                float2 f = __half22float2(*(__half2*)&acc[mt][nt][rr]);
                const int col = wn * 64 + nt * 8 + (lane & 3) * 2;
                float d0 = fmaxf(fmaf(-2.f, f.x, x2v + c2s[col]), 0.f);
                float d1 = fmaxf(fmaf(-2.f, f.y, x2v + c2s[col + 1]), 0.f);
                rsum += frcp(1.f + d0) + frcp(1.f + d1);
            }
            rsum += __shfl_xor_sync(0xffffffffu, rsum, 1);
            rsum += __shfl_xor_sync(0xffffffffu, rsum, 2);
            if ((lane & 3) == 0) rss[wn * 64 + row] = rsum;
        }
    }
    __syncthreads();

    // ---- epilogue pass 2: normalize (recompute q in fp32) and store ----
    #pragma unroll
    for (int mt = 0; mt < 2; mt++) {
        #pragma unroll
        for (int rr = 0; rr < 2; rr++) {
            const int row = wm * 32 + mt * 16 + (lane >> 2) + rr * 8;
            const float x2v = x2s[row];
            float s = 0.f;
            #pragma unroll
            for (int g = 0; g < 8; g++) s += rss[g * 64 + row];
            const float inv = frcp(s);
            float* orow = out + (row0 + row) * KDIM;
            #pragma unroll
            for (int nt = 0; nt < 8; nt++) {
                float2 f = __half22float2(*(__half2*)&acc[mt][nt][rr]);
                const int col = wn * 64 + nt * 8 + (lane & 3) * 2;
                float d0 = fmaxf(fmaf(-2.f, f.x, x2v + c2s[col]), 0.f);
                float d1 = fmaxf(fmaf(-2.f, f.y, x2v + c2s[col + 1]), 0.f);
                *(float2*)&orow[col] = make_float2(frcp(1.f + d0) * inv, frcp(1.f + d1) * inv);
            }
        }
    }
}

extern "C" void kernel_launch(void* const* d_in, const int* in_sizes, int n_in,
                              void* d_out, int out_size) {
    const float* x        = (const float*)d_in[0];
    const float* clusters = (const float*)d_in[1];
    float* out = (float*)d_out;
    int n = in_sizes[0] / DDIM;   // 131072

    cudaFuncSetAttribute(cluster_kernel, cudaFuncAttributeMaxDynamicSharedMemorySize, SMEM_TOTAL);
    prep_kernel<<<KDIM, 128>>>(clusters);
    cluster_kernel<<<n / BM, NTH, SMEM_TOTAL>>>(x, out);
}

// round 10
// speedup vs baseline: 1.0383x; 1.0383x over previous
#include <cuda_runtime.h>
#include <cuda_fp16.h>
#include <cstdint>

#define DDIM 512
#define KDIM 512
#define BM   64
#define NTH  512
#define NCH  32
#define NTILES 2048
#define GRID 152

// static scratch (no allocations allowed)
__device__ __half g_cb[KDIM * DDIM];   // clusters fp16 [K][D]
__device__ float g_c2[KDIM];

// ---- smem layout (bytes, dynamic) ----
#define ABUF    65536u                 // one A buffer: 64 rows x 1024B swizzled f16
#define BSTG    16384u                 // one B stage: 512 rows x 32B, XOR swizzle
#define XSTG    8192u                  // one x staging slice: 4 rows fp32
#define OFF_A   0u                     // 2 x 65536 -> 131072
#define OFF_B   131072u                // 3 x 16384 -> 180224
#define OFF_XS  180224u                // 3 x 8192  -> 204800
#define OFF_C2  204800u                // 512*4     -> 206848
#define OFF_X2  206848u                // 2 x 64 x 4 floats -> 208896
#define OFF_RS  208896u                // 8 x 64 floats -> 210944
#define SMEM_TOTAL 210944u

// ---------------- helpers ----------------
__device__ __forceinline__ float frcp(float a) {
    float r; asm("rcp.approx.ftz.f32 %0, %1;" : "=f"(r) : "f"(a)); return r;
}
__device__ __forceinline__ uint32_t pkh(float a, float b) {
    __half2 h = __floats2half2_rn(a, b);
    return *reinterpret_cast<uint32_t*>(&h);
}
__device__ __forceinline__ void cp16(uint32_t dst, const void* src) {
    asm volatile("cp.async.cg.shared.global [%0], [%1], 16;"
                 :: "r"(dst), "l"(__cvta_generic_to_global(src)) : "memory");
}
#define CP_COMMIT() asm volatile("cp.async.commit_group;" ::: "memory")
template <int N>
__device__ __forceinline__ void cp_wait() {
    asm volatile("cp.async.wait_group %0;" :: "n"(N) : "memory");
}
__device__ __forceinline__ void ldsm4(uint32_t* r, uint32_t a) {
    asm volatile("ldmatrix.sync.aligned.m8n8.x4.shared.b16 {%0,%1,%2,%3}, [%4];"
                 : "=r"(r[0]), "=r"(r[1]), "=r"(r[2]), "=r"(r[3]) : "r"(a));
}
__device__ __forceinline__ void mma_f16(uint32_t* c, const uint32_t* a, uint32_t b0, uint32_t b1) {
    asm volatile("mma.sync.aligned.m16n8k16.row.col.f16.f16.f16.f16 "
                 "{%0,%1}, {%2,%3,%4,%5}, {%6,%7}, {%0,%1};"
                 : "+r"(c[0]), "+r"(c[1])
                 : "r"(a[0]), "r"(a[1]), "r"(a[2]), "r"(a[3]), "r"(b0), "r"(b1));
}

// ---------------- prep: clusters -> fp16, c2 fp32 ----------------
__global__ void prep_kernel(const float* __restrict__ clusters) {
    int k = blockIdx.x, tid = threadIdx.x;
    const float* row = clusters + (size_t)k * DDIM;
    float s = 0.f;
    for (int d = tid; d < DDIM; d += 128) {
        float v = row[d];
        s += v * v;
        g_cb[(size_t)k * DDIM + d] = __float2half(v);
    }
    #pragma unroll
    for (int o = 16; o > 0; o >>= 1) s += __shfl_xor_sync(0xffffffffu, s, o);
    __shared__ float red[4];
    if ((tid & 31) == 0) red[tid >> 5] = s;
    __syncthreads();
    if (tid == 0) g_c2[k] = red[0] + red[1] + red[2] + red[3];
}

// ---------------- main fused persistent kernel ----------------
// 152 persistent CTAs; each processes tiles t = bid, bid+152, ...
// Tile: 64 rows x all 512 cols. Warp grid 2(M) x 8(N), warp tile 32x64, f16 acc.
// While tile t computes, x(t+152) streams (cp.async fp32) + converts into the
// other A buffer. B streams in a rolling 3-slot ring with 2-chunk slack.
__global__ void __launch_bounds__(NTH, 1)
cluster_kernel(const float* __restrict__ x, float* __restrict__ out) {
    extern __shared__ char smem[];
    float* c2s = (float*)(smem + OFF_C2);
    float* x2p = (float*)(smem + OFF_X2);   // [2][64][4]
    float* rss = (float*)(smem + OFF_RS);   // [8][64]

    const int tid = threadIdx.x, lane = tid & 31, wid = tid >> 5;
    const int wm = wid & 1, wn = wid >> 1;          // 2 x 8 warp grid
    const uint32_t sA = (uint32_t)__cvta_generic_to_shared(smem + OFF_A);
    const uint32_t sB = (uint32_t)__cvta_generic_to_shared(smem + OFF_B);
    const uint32_t sX = (uint32_t)__cvta_generic_to_shared(smem + OFF_XS);

    // B loader: k-chunk kc (cols [kc*16,kc*16+16)) of all 512 rows into slot
    auto loadB = [&](int kc, int slot) {
        #pragma unroll
        for (int i = 0; i < 2; i++) {
            int idx = tid + i * NTH;                // 0..1023
            int brow = idx >> 1, seg = (idx & 1) << 4;
            uint32_t dst = sB + slot * BSTG + brow * 32 + (seg ^ ((brow & 4) << 2));
            const char* src = (const char*)g_cb + (size_t)brow * (DDIM * 2) + kc * 32 + seg;
            cp16(dst, src);
        }
    };
    // convert staged fp32 slice s (rows 4s..4s+3) into A buffer abN, + x2 partials
    auto convS = [&](int s, int abN) {
        float4 v = *(const float4*)(smem + OFF_XS + (s % 3) * XSTG + tid * 16);
        int arow = s * 4 + (tid >> 7);
        uint32_t cb = (uint32_t)(tid & 127) * 8;
        uint2 w = make_uint2(pkh(v.x, v.y), pkh(v.z, v.w));
        *(uint2*)(smem + OFF_A + abN * ABUF + arow * 1024 + (cb ^ ((arow & 7u) << 4))) = w;
        float x2a = v.x * v.x + v.y * v.y + v.z * v.z + v.w * v.w;
        #pragma unroll
        for (int o = 16; o > 0; o >>= 1) x2a += __shfl_xor_sync(0xffffffffu, x2a, o);
        if (lane == 0) x2p[abN * 256 + arow * 4 + ((tid >> 5) & 3)] = x2a;
    };

    // prologue: prefetch B chunks 0,1 (groups 0,1), then direct-convert tile0's A
    loadB(0, 0); CP_COMMIT();
    loadB(1, 1); CP_COMMIT();

    for (int i = tid; i < KDIM; i += NTH) c2s[i] = g_c2[i];

    int tile = blockIdx.x;
    {
        const int arow = tid >> 3, a8 = tid & 7;    // 8 threads/row, 64 floats each
        const float* src = x + ((size_t)tile * BM + arow) * DDIM + a8 * 64;
        float x2a = 0.f;
        #pragma unroll
        for (int j = 0; j < 8; j++) {
            float4 u = *(const float4*)(src + j * 8);
            float4 v = *(const float4*)(src + j * 8 + 4);
            x2a += u.x * u.x + u.y * u.y + u.z * u.z + u.w * u.w;
            x2a += v.x * v.x + v.y * v.y + v.z * v.z + v.w * v.w;
            uint4 w = make_uint4(pkh(u.x, u.y), pkh(u.z, u.w), pkh(v.x, v.y), pkh(v.z, v.w));
            uint32_t cb = (uint32_t)(a8 * 128 + j * 16);
            *(uint4*)(smem + OFF_A + arow * 1024 + (cb ^ ((arow & 7u) << 4))) = w;
        }
        x2a += __shfl_xor_sync(0xffffffffu, x2a, 1);
        x2a += __shfl_xor_sync(0xffffffffu, x2a, 2);
        x2a += __shfl_xor_sync(0xffffffffu, x2a, 4);
        if ((tid & 7) == 0) x2p[arow * 4] = x2a;
        else if ((tid & 7) < 4) x2p[arow * 4 + (tid & 7)] = 0.f;
    }

    const uint32_t lmr = lane & 15, lmc = (lane >> 4) * 16;
    const uint32_t xr  = (lmr & 7u) << 4;
    const uint32_t bro = (uint32_t)(wn * 64 + lmr) * 32u + (lmc ^ ((lmr & 4u) << 2));

    int ab = 0;       // A buffer of current tile
    int bs = 0;       // B slot of current chunk (rolls across tiles)

    for (; tile < NTILES; tile += GRID) {
        const bool hasNext = (tile + GRID) < NTILES;
        const char* xnext = (const char*)(x + (size_t)(tile + GRID) * BM * DDIM);

        uint32_t acc[2][8][2];
        #pragma unroll
        for (int mt = 0; mt < 2; mt++)
            #pragma unroll
            for (int nt = 0; nt < 8; nt++) { acc[mt][nt][0] = 0u; acc[mt][nt][1] = 0u; }

        const uint32_t aro0 = sA + ab * ABUF + (uint32_t)(wm * 32 + lmr) * 1024u;
        const uint32_t aro1 = aro0 + 16u * 1024u;

        #pragma unroll 1
        for (int c = 0; c < NCH; c++) {
            cp_wait<1>();                 // B(c) + x-slice(issued at c-2) landed
            __syncthreads();
            int ps = bs + 2; if (ps >= 3) ps -= 3;
            if (hasNext || c < NCH - 2) loadB((c + 2) & 31, ps);
            if (hasNext && !(c & 1)) {    // even chunk: stage x slice c/2 of next tile
                int s = c >> 1;
                cp16(sX + (s % 3) * XSTG + tid * 16, xnext + (size_t)s * XSTG + tid * 16);
            }
            CP_COMMIT();                  // exactly ONE group per chunk (may be empty)
            if (hasNext && !(c & 1) && c >= 2)
                convS((c - 2) >> 1, ab ^ 1);

            // compute chunk c
            const uint32_t acb = ((uint32_t)(c * 32) + lmc) ^ xr;
            uint32_t a0[4], a1[4];
            ldsm4(a0, aro0 + acb);
            ldsm4(a1, aro1 + acb);
            const uint32_t bbase = sB + bs * BSTG + bro;
            #pragma unroll
            for (int bt = 0; bt < 4; bt++) {
                uint32_t b[4];
                ldsm4(b, bbase + bt * 512);
                mma_f16(acc[0][2 * bt + 0], a0, b[0], b[2]);
                mma_f16(acc[0][2 * bt + 1], a0, b[1], b[3]);
                mma_f16(acc[1][2 * bt + 0], a1, b[0], b[2]);
                mma_f16(acc[1][2 * bt + 1], a1, b[1], b[3]);
            }
            bs++; if (bs >= 3) bs = 0;
        }
        if (hasNext) {
            cp_wait<1>();                 // slice 15 (issued chunk 30) landed
            convS(15, ab ^ 1);            // each thread reads its self-issued bytes
        }

        // ---- epilogue pass 1: row sums ----
        #pragma unroll
        for (int mt = 0; mt < 2; mt++) {
            #pragma unroll
            for (int rr = 0; rr < 2; rr++) {
                const int row = wm * 32 + mt * 16 + (lane >> 2) + rr * 8;
                const float x2v = x2p[ab * 256 + row * 4] + x2p[ab * 256 + row * 4 + 1]
                                + x2p[ab * 256 + row * 4 + 2] + x2p[ab * 256 + row * 4 + 3];
                float rsum = 0.f;
                #pragma unroll
                for (int nt = 0; nt < 8; nt++) {
                    float2 f = __half22float2(*(__half2*)&acc[mt][nt][rr]);
                    const int col = wn * 64 + nt * 8 + (lane & 3) * 2;
                    float d0 = fmaxf(fmaf(-2.f, f.x, x2v + c2s[col]), 0.f);
                    float d1 = fmaxf(fmaf(-2.f, f.y, x2v + c2s[col + 1]), 0.f);
                    rsum += frcp(1.f + d0) + frcp(1.f + d1);
                }
                rsum += __shfl_xor_sync(0xffffffffu, rsum, 1);
                rsum += __shfl_xor_sync(0xffffffffu, rsum, 2);
                if ((lane & 3) == 0) rss[wn * 64 + row] = rsum;
            }
        }
        __syncthreads();

        // ---- epilogue pass 2: normalize (recompute q fp32) and store ----
        #pragma unroll
        for (int mt = 0; mt < 2; mt++) {
            #pragma unroll
            for (int rr = 0; rr < 2; rr++) {
                const int row = wm * 32 + mt * 16 + (lane >> 2) + rr * 8;
                const float x2v = x2p[ab * 256 + row * 4] + x2p[ab * 256 + row * 4 + 1]
                                + x2p[ab * 256 + row * 4 + 2] + x2p[ab * 256 + row * 4 + 3];
                float s = 0.f;
                #pragma unroll
                for (int g = 0; g < 8; g++) s += rss[g * 64 + row];
                const float inv = frcp(s);
                float* orow = out + ((size_t)tile * BM + row) * KDIM;
                #pragma unroll
                for (int nt = 0; nt < 8; nt++) {
                    float2 f = __half22float2(*(__half2*)&acc[mt][nt][rr]);
                    const int col = wn * 64 + nt * 8 + (lane & 3) * 2;
                    float d0 = fmaxf(fmaf(-2.f, f.x, x2v + c2s[col]), 0.f);
                    float d1 = fmaxf(fmaf(-2.f, f.y, x2v + c2s[col + 1]), 0.f);
                    *(float2*)&orow[col] = make_float2(frcp(1.f + d0) * inv, frcp(1.f + d1) * inv);
                }
            }
        }
        ab ^= 1;
    }
}

extern "C" void kernel_launch(void* const* d_in, const int* in_sizes, int n_in,
                              void* d_out, int out_size) {
    const float* x        = (const float*)d_in[0];
    const float* clusters = (const float*)d_in[1];
    float* out = (float*)d_out;

    cudaFuncSetAttribute(cluster_kernel, cudaFuncAttributeMaxDynamicSharedMemorySize, SMEM_TOTAL);
    prep_kernel<<<KDIM, 128>>>(clusters);
    cluster_kernel<<<GRID, NTH, SMEM_TOTAL>>>(x, out);
}